// round 9
// baseline (speedup 1.0000x reference)
#include <cuda_runtime.h>
#include <math.h>

#define ND   768
#define NB   8
#define NCH  3
#define NMIX 5
#define NS   10
#define HH   10
#define PI2f 6.28318530717958647692f
#define ZITTERf 1e-4f
#define NPLANE (NB*NCH*NMIX)          // 120
#define LOG2Ef 1.4426950408889634f

__device__ float    g_feat[NPLANE * ND];   // zero-init; kA atomics; k34 reads then re-zeroes
__device__ float    g_hmean[NB * NCH * HH];
__device__ float    g_w[NB * NCH * NMIX];
__device__ unsigned g_ctr;                 // zero-init; k34 last-block counter (self-resetting)

__device__ __forceinline__ float ex2(float x) {
    float y; asm("ex2.approx.ftz.f32 %0, %1;" : "=f"(y) : "f"(x)); return y;
}

// ---------------------------------------------------------------------------
// Kernel A: feature[bc,m,i] = sum_j K_m(i,j)*yc[j], trig-separated.
// Tile: 64 i x 256 j. Thread: i = t>>2, jq = t&3 over 64 consecutive j.
// ---------------------------------------------------------------------------
#define JPA 280    // padded table stride for 256 j

__global__ void __launch_bounds__(256) kA_feat(const float* __restrict__ xc,
                                               const float* __restrict__ yc,
                                               const float* __restrict__ mu,
                                               const float* __restrict__ inv_std)
{
    int bc  = blockIdx.z;                 // b*3 + c
    int b   = bc / NCH, c = bc - b*NCH;
    int it  = blockIdx.y;
    int jt0 = blockIdx.x * 256;
    int t   = threadIdx.x;

    __shared__ float sC[NMIX*JPA], sS[NMIX*JPA], sXj[JPA];

    float Bv[NMIX], Pv[NMIX];
    #pragma unroll
    for (int m = 0; m < NMIX; m++) {
        float s = inv_std[m];
        Bv[m] = -0.5f * PI2f * PI2f * LOG2Ef * s * s;
        Pv[m] = PI2f * mu[m];
    }

    {   // table setup: every thread owns one j
        int j  = t;
        int gj = jt0 + j;
        float xjv = xc[(b*ND + gj)*NCH + c];
        float yjv = yc[(b*ND + gj)*NCH + c];
        int pj = j + ((j >> 6) << 3);
        sXj[pj] = xjv;
        #pragma unroll
        for (int m = 0; m < NMIX; m++) {
            float sn, cs;
            __sincosf(Pv[m] * xjv, &sn, &cs);
            sC[m*JPA + pj] = cs * yjv;
            sS[m*JPA + pj] = sn * yjv;
        }
    }
    __syncthreads();

    int i_loc = t >> 2, jq = t & 3;
    int gi = it*64 + i_loc;
    float xi = xc[(b*ND + gi)*NCH + c];

    float cI[NMIX], sI[NMIX];
    #pragma unroll
    for (int m = 0; m < NMIX; m++)
        __sincosf(Pv[m] * xi, &sI[m], &cI[m]);

    float accC[NMIX], accS[NMIX];
    #pragma unroll
    for (int m = 0; m < NMIX; m++) { accC[m] = 0.f; accS[m] = 0.f; }

    int gbase = jq * 72;
    #pragma unroll 4
    for (int ch = 0; ch < 16; ch++) {
        int off = gbase + ch*4;
        float4 xv = *reinterpret_cast<const float4*>(&sXj[off]);
        float d0 = xi - xv.x, d1 = xi - xv.y, d2 = xi - xv.z, d3 = xi - xv.w;
        float e0 = d0*d0, e1 = d1*d1, e2 = d2*d2, e3 = d3*d3;
        #pragma unroll
        for (int m = 0; m < NMIX; m++) {
            float Bm = Bv[m];
            float4 cj = *reinterpret_cast<const float4*>(&sC[m*JPA + off]);
            float4 sj = *reinterpret_cast<const float4*>(&sS[m*JPA + off]);
            float v0 = ex2(Bm*e0), v1 = ex2(Bm*e1), v2 = ex2(Bm*e2), v3 = ex2(Bm*e3);
            accC[m] += v0*cj.x + v1*cj.y + v2*cj.z + v3*cj.w;
            accS[m] += v0*sj.x + v1*sj.y + v2*sj.z + v3*sj.w;
        }
    }

    #pragma unroll
    for (int m = 0; m < NMIX; m++) {
        accC[m] += __shfl_xor_sync(0xffffffffu, accC[m], 1);
        accC[m] += __shfl_xor_sync(0xffffffffu, accC[m], 2);
        accS[m] += __shfl_xor_sync(0xffffffffu, accS[m], 1);
        accS[m] += __shfl_xor_sync(0xffffffffu, accS[m], 2);
    }
    if (jq == 0) {
        #pragma unroll
        for (int m = 0; m < NMIX; m++)
            atomicAdd(&g_feat[(bc*NMIX + m)*ND + gi],
                      cI[m]*accC[m] + sI[m]*accS[m]);
    }
}

// ---------------------------------------------------------------------------
// Kernel 34: per-bc hmean (+ re-zero g_feat), then last block runs the MLP
// + Gumbel-softmax.
// ---------------------------------------------------------------------------
__global__ void __launch_bounds__(256) k34_hmean_mlp(
        const float* __restrict__ yc,
        const float* __restrict__ W1, const float* __restrict__ b1,
        const float* __restrict__ W2, const float* __restrict__ b2,
        const float* __restrict__ W3, const float* __restrict__ b3,
        const float* __restrict__ W4, const float* __restrict__ b4,
        const float* __restrict__ W5, const float* __restrict__ b5,
        const float* __restrict__ unif)
{
    int bc = blockIdx.x;
    int b  = bc / NCH, c = bc - b*NCH;
    int t  = threadIdx.x;

    __shared__ float sW[HH*6], sb[HH], sh[HH];
    __shared__ float w2[300], w3[100], w4[100], w5[150];
    __shared__ float sb2[HH], sb3[HH], sb4[HH], sb5[15];
    __shared__ float su[NB*NS*NCH*NMIX];          // 1200 floats
    __shared__ float shm[NB][30], haL[NB][HH], hbL[NB][HH], ll[NB][15], swacc[NB][15];
    __shared__ bool  isLast;

    for (int u = t; u < 300; u += 256) w2[u] = W2[u];
    for (int u = t; u < 1200; u += 256) su[u] = unif[u];
    if (t < 100) { w3[t] = W3[t]; w4[t] = W4[t]; }
    if (t < 150) w5[t] = W5[t];
    if (t < HH)  { sb2[t] = b2[t]; sb3[t] = b3[t]; sb4[t] = b4[t]; }
    if (t < 15)  sb5[t] = b5[t];
    if (t < HH*6) sW[t] = W1[t];
    if (t < HH)  { sb[t] = b1[t]; sh[t] = 0.f; }
    __syncthreads();

    float hacc[HH];
    #pragma unroll
    for (int k = 0; k < HH; k++) hacc[k] = 0.f;

    for (int i = t; i < ND; i += 256) {
        float ycv = yc[(b*ND + i)*NCH + c];
        float f[6];
        #pragma unroll
        for (int m = 0; m < NMIX; m++) {
            int idx = (bc*NMIX + m)*ND + i;
            f[m] = g_feat[idx] + ZITTERf * ycv;
            g_feat[idx] = 0.f;                    // restore invariant for next replay
        }
        f[5] = ycv;
        #pragma unroll
        for (int k = 0; k < HH; k++) {
            float s = sb[k];
            #pragma unroll
            for (int u = 0; u < 6; u++) s += sW[k*6 + u] * f[u];
            hacc[k] += fmaxf(s, 0.f);
        }
    }
    #pragma unroll
    for (int k = 0; k < HH; k++) atomicAdd(&sh[k], hacc[k]);
    __syncthreads();
    if (t < HH)
        g_hmean[b*(NCH*HH) + c*HH + t] = sh[t] * (1.0f/ND);

    __threadfence();
    __syncthreads();
    if (t == 0) isLast = (atomicAdd(&g_ctr, 1u) == (unsigned)(NB*NCH - 1));
    __syncthreads();
    if (!isLast) return;
    if (t == 0) g_ctr = 0;

    if (t < NB*30) {
        const volatile float* hmv = g_hmean;
        shm[t/30][t%30] = hmv[t];
    }
    if (t < NB*15) swacc[t/15][t%15] = 0.f;
    __syncthreads();

    if (t < NB*HH) {
        int bb = t/HH, k = t%HH;
        float s = sb2[k];
        #pragma unroll
        for (int u = 0; u < 30; u++) s += w2[k*30+u] * shm[bb][u];
        haL[bb][k] = fmaxf(s, 0.f);
    }
    __syncthreads();
    if (t < NB*HH) {
        int bb = t/HH, k = t%HH;
        float s = sb3[k];
        #pragma unroll
        for (int u = 0; u < HH; u++) s += w3[k*HH+u] * haL[bb][u];
        hbL[bb][k] = fmaxf(s, 0.f);
    }
    __syncthreads();
    if (t < NB*HH) {
        int bb = t/HH, k = t%HH;
        float s = sb4[k];
        #pragma unroll
        for (int u = 0; u < HH; u++) s += w4[k*HH+u] * hbL[bb][u];
        haL[bb][k] = fmaxf(s, 0.f);
    }
    __syncthreads();
    if (t < NB*15) {
        int bb = t/15, n = t%15;
        float s = sb5[n];
        #pragma unroll
        for (int k = 0; k < HH; k++) s += w5[n*HH+k] * haL[bb][k];
        ll[bb][n] = s;
    }
    __syncthreads();

    if (t < NB*NS*NCH) {
        int bb = t / (NS*NCH);
        int rem = t % (NS*NCH);
        int s_ = rem / NCH, cc = rem % NCH;
        float z[NMIX], mx = -1e30f;
        #pragma unroll
        for (int m = 0; m < NMIX; m++) {
            float u = su[((bb*NS + s_)*NCH + cc)*NMIX + m];
            float g = -__logf(-__logf(u + 1e-20f));
            z[m] = (g + ll[bb][cc*NMIX + m]) * 10.0f;   // 1/TEMP
            mx = fmaxf(mx, z[m]);
        }
        float sum = 0.f;
        #pragma unroll
        for (int m = 0; m < NMIX; m++) { z[m] = __expf(z[m] - mx); sum += z[m]; }
        float inv = 1.0f / (sum * (float)NS);
        #pragma unroll
        for (int m = 0; m < NMIX; m++)
            atomicAdd(&swacc[bb][cc*NMIX + m], z[m] * inv);
    }
    __syncthreads();
    if (t < NB*NCH*NMIX)
        g_w[t] = swacc[t/(NCH*NMIX)][t%(NCH*NMIX)];
}

// ---------------------------------------------------------------------------
// Kernel B (rebuilt): out[b,i,j,c] = sum_m w*K + diag. Trig-separated,
// full grid, tile 24 i x 256 j. j-tables (cos*w, sin*w) read as
// lane-consecutive float4 (conflict-free); i-side sin/cos via broadcast LDS.
// Warp = 3 rows processed per chunk-load (table LDS amortized 3x).
// ---------------------------------------------------------------------------
#define KB_IT 24
#define KB_JT 256

__global__ void __launch_bounds__(256, 2) kB_out(float* __restrict__ out,
                                                 const float* __restrict__ xc,
                                                 const float* __restrict__ mu,
                                                 const float* __restrict__ inv_std,
                                                 const float* __restrict__ likerr)
{
    int b   = blockIdx.z;
    int it0 = blockIdx.y * KB_IT;
    int jt0 = blockIdx.x * KB_JT;
    int t   = threadIdx.x;

    __shared__ float sC[NCH*NMIX*KB_JT];   // (cos(P*xj) * w)  [c*5+m][j]
    __shared__ float sS[NCH*NMIX*KB_JT];   // (sin(P*xj) * w)
    __shared__ float sXj[NCH*KB_JT];       // xj per channel
    __shared__ float sFI[KB_IT*30];        // i-side: [row][c*10 + m*2 + {cos,sin}]

    float Bv[NMIX], Pv[NMIX];
    #pragma unroll
    for (int m = 0; m < NMIX; m++) {
        float s = inv_std[m];
        Bv[m] = -0.5f * PI2f * PI2f * LOG2Ef * s * s;
        Pv[m] = PI2f * mu[m];
    }
    float sd[NCH];
    #pragma unroll
    for (int c = 0; c < NCH; c++) {
        float l = fminf(fmaxf(likerr[c], 0.1f), 1.0f);
        sd[c] = ZITTERf + l*l;
    }

    {   // j tables: one j per thread
        int j = t;
        #pragma unroll
        for (int c = 0; c < NCH; c++) {
            float xjv = xc[(b*ND + jt0 + j)*NCH + c];
            sXj[c*KB_JT + j] = xjv;
            #pragma unroll
            for (int m = 0; m < NMIX; m++) {
                float sn, cs;
                __sincosf(Pv[m] * xjv, &sn, &cs);
                float wv = g_w[(b*NCH + c)*NMIX + m];
                sC[(c*NMIX + m)*KB_JT + j] = cs * wv;
                sS[(c*NMIX + m)*KB_JT + j] = sn * wv;
            }
        }
    }
    // i-side factors: 24 rows x 15 (c,m)
    for (int u = t; u < KB_IT*15; u += 256) {
        int row = u / 15, cm = u % 15, c = cm / 5, m = cm % 5;
        float xiv = xc[(b*ND + it0 + row)*NCH + c];
        float sn, cs;
        __sincosf(Pv[m] * xiv, &sn, &cs);
        sFI[row*30 + cm*2    ] = cs;
        sFI[row*30 + cm*2 + 1] = sn;
    }
    __syncthreads();

    int w = t >> 5, lane = t & 31;
    int r0 = w * 3;                        // 8 warps x 3 rows = 24

    // xi values for this warp's 3 rows (registers)
    float xi[3][NCH];
    #pragma unroll
    for (int r = 0; r < 3; r++)
        #pragma unroll
        for (int c = 0; c < NCH; c++)
            xi[r][c] = xc[(b*ND + it0 + r0 + r)*NCH + c];

    #pragma unroll
    for (int p = 0; p < 2; p++) {
        int ch = p*32 + lane;
        int j0 = ch * 4;                   // local j of this chunk

        float o[3][12];
        #pragma unroll
        for (int r = 0; r < 3; r++)
            #pragma unroll
            for (int u = 0; u < 12; u++) o[r][u] = 0.f;

        #pragma unroll
        for (int c = 0; c < NCH; c++) {
            float4 xv = *reinterpret_cast<const float4*>(&sXj[c*KB_JT + j0]);
            float e[3][4];
            #pragma unroll
            for (int r = 0; r < 3; r++) {
                float x = xi[r][c];
                float d0 = x - xv.x, d1 = x - xv.y, d2 = x - xv.z, d3 = x - xv.w;
                e[r][0] = d0*d0; e[r][1] = d1*d1; e[r][2] = d2*d2; e[r][3] = d3*d3;
            }
            #pragma unroll
            for (int m = 0; m < NMIX; m++) {
                float Bm = Bv[m];
                float4 cj = *reinterpret_cast<const float4*>(&sC[(c*NMIX + m)*KB_JT + j0]);
                float4 sj = *reinterpret_cast<const float4*>(&sS[(c*NMIX + m)*KB_JT + j0]);
                #pragma unroll
                for (int r = 0; r < 3; r++) {
                    float cIv = sFI[(r0 + r)*30 + (c*NMIX + m)*2];       // broadcast
                    float sIv = sFI[(r0 + r)*30 + (c*NMIX + m)*2 + 1];
                    o[r][0*NCH + c] += ex2(Bm*e[r][0]) * (cIv*cj.x + sIv*sj.x);
                    o[r][1*NCH + c] += ex2(Bm*e[r][1]) * (cIv*cj.y + sIv*sj.y);
                    o[r][2*NCH + c] += ex2(Bm*e[r][2]) * (cIv*cj.z + sIv*sj.z);
                    o[r][3*NCH + c] += ex2(Bm*e[r][3]) * (cIv*cj.w + sIv*sj.w);
                }
            }
        }

        #pragma unroll
        for (int r = 0; r < 3; r++) {
            int gi = it0 + r0 + r;
            int jj = gi - (jt0 + j0);
            if (jj >= 0 && jj < 4) {       // diagonal element inside this chunk
                #pragma unroll
                for (int c = 0; c < NCH; c++) o[r][jj*NCH + c] += sd[c];
            }
            size_t base = ((size_t)(b*ND + gi)*ND + jt0 + j0) * NCH;
            float4* pp = reinterpret_cast<float4*>(out + base);
            pp[0] = make_float4(o[r][0], o[r][1], o[r][2],  o[r][3]);
            pp[1] = make_float4(o[r][4], o[r][5], o[r][6],  o[r][7]);
            pp[2] = make_float4(o[r][8], o[r][9], o[r][10], o[r][11]);
        }
    }
}

// ---------------------------------------------------------------------------
extern "C" void kernel_launch(void* const* d_in, const int* in_sizes, int n_in,
                              void* d_out, int out_size)
{
    const float* xc      = (const float*)d_in[0];
    const float* yc      = (const float*)d_in[1];
    const float* mu      = (const float*)d_in[2];
    const float* inv_std = (const float*)d_in[3];
    const float* likerr  = (const float*)d_in[4];
    const float* unif    = (const float*)d_in[5];
    const float* W1 = (const float*)d_in[6];  const float* b1 = (const float*)d_in[7];
    const float* W2 = (const float*)d_in[8];  const float* b2 = (const float*)d_in[9];
    const float* W3 = (const float*)d_in[10]; const float* b3 = (const float*)d_in[11];
    const float* W4 = (const float*)d_in[12]; const float* b4 = (const float*)d_in[13];
    const float* W5 = (const float*)d_in[14]; const float* b5 = (const float*)d_in[15];
    float* out = (float*)d_out;

    kA_feat <<< dim3(3, ND/64, NB*NCH), 256 >>>(xc, yc, mu, inv_std);
    k34_hmean_mlp <<< NB*NCH, 256 >>>(yc, W1, b1, W2, b2, W3, b3, W4, b4, W5, b5, unif);
    kB_out  <<< dim3(ND/KB_JT, ND/KB_IT, NB), 256 >>>(out, xc, mu, inv_std, likerr);
}